// round 16
// baseline (speedup 1.0000x reference)
#include <cuda_runtime.h>
#include <cuda_fp16.h>
#include <math.h>
#include <stdint.h>

#define N_NODES 50000
#define E_EDGES 800000
#define HID 256
#define NCLASS 10
#define NGRAPH 512
#define NB_SCAN ((N_NODES + 1023) / 1024)   // 49

// ---------------- device scratch (static; no cudaMalloc allowed) --------------
__device__ __half  g_hh[(size_t)N_NODES * HID];     // fp16 activations (agg out)
__device__ __half  g_h2h[(size_t)N_NODES * HID];    // fp16 pre-agg (dinv-scaled)
__device__ __half  g_Wt16[HID * HID];               // conv_W[1] fp16, [N][K]
__device__ __half  g_Wf16[HID * HID];               // fused We@Wc0 fp16, [N][K]
__device__ float   g_bf[HID];                       // fused bias be@Wc0
__device__ float   g_dinv[N_NODES];
__device__ int     g_deg[N_NODES];
__device__ int     g_indptr[N_NODES + 1];
__device__ int     g_cursor[N_NODES];
__device__ int     g_csrsrc[E_EDGES + N_NODES];
__device__ int     g_gstart[NGRAPH + 1];
__device__ int     g_part[64];

// ---------------- helpers -----------------------------------------------------
__device__ __forceinline__ uint32_t smem_u32(const void* p) {
    uint32_t a;
    asm("{ .reg .u64 t; cvta.to.shared.u64 t, %1; cvt.u32.u64 %0, t; }" : "=r"(a) : "l"(p));
    return a;
}
__device__ __forceinline__ uint32_t h2_bits(__half2 h) {
    return *(uint32_t*)&h;
}
__device__ __forceinline__ void mma_f16(float* d, const uint32_t* a, const uint32_t* b) {
    asm volatile(
        "mma.sync.aligned.m16n8k16.row.col.f32.f16.f16.f32 "
        "{%0,%1,%2,%3}, {%4,%5,%6,%7}, {%8,%9}, {%0,%1,%2,%3};"
        : "+f"(d[0]), "+f"(d[1]), "+f"(d[2]), "+f"(d[3])
        : "r"(a[0]), "r"(a[1]), "r"(a[2]), "r"(a[3]), "r"(b[0]), "r"(b[1]));
}
#define CP_ASYNC16(dst, src, sz) \
    asm volatile("cp.async.cg.shared.global [%0], [%1], 16, %2;" :: "r"(dst), "l"(src), "r"(sz))
#define CP_COMMIT()   asm volatile("cp.async.commit_group;" ::: "memory")
#define CP_WAIT(n)    asm volatile("cp.async.wait_group %0;" :: "n"(n) : "memory")

// ---------------- CSR pipeline (stream B) -------------------------------------
__global__ void k_zero() {
    int i = blockIdx.x * blockDim.x + threadIdx.x;
    if (i < N_NODES) g_deg[i] = 0;
    if (i < 64) g_part[i] = 0;
}
__global__ void k_count_deg(const int* __restrict__ col) {
    int stride = gridDim.x * blockDim.x;
    for (int e = blockIdx.x * blockDim.x + threadIdx.x; e < E_EDGES; e += stride)
        atomicAdd(&g_deg[col[e]], 1);
}
// single-pass multi-block scan: local smem scan + published totals + spin.
// 49 blocks of 1024 all resident (148 SMs) -> no deadlock.
__global__ void k_scan() {
    __shared__ int s[1024];
    __shared__ int ssum;
    int tid = threadIdx.x;
    int bid = blockIdx.x;
    int i = bid * 1024 + tid;
    int v = 0;
    if (i < N_NODES) {
        int d = g_deg[i] + 1;
        v = d;
        g_dinv[i] = rsqrtf((float)d);
    }
    s[tid] = v;
    __syncthreads();
    for (int off = 1; off < 1024; off <<= 1) {
        int t = (tid >= off) ? s[tid - off] : 0;
        __syncthreads();
        s[tid] += t;
        __syncthreads();
    }
    if (tid == 0) {
        ssum = 0;
        __threadfence();
        g_part[bid] = s[1023];   // totals always >= 1: nonzero doubles as ready flag
    }
    __syncthreads();
    int off = 0;
    if (tid < bid) {             // bid <= 48 < 1024
        int pv;
        do { pv = ((volatile int*)g_part)[tid]; } while (pv == 0);
        off = pv;
    }
    if (off) atomicAdd(&ssum, off);
    __syncthreads();
    int base = ssum;
    if (i < N_NODES) {
        int val = base + s[tid] - v;
        g_indptr[i] = val;
        g_cursor[i] = val;
    }
    if (i == 0) g_indptr[N_NODES] = E_EDGES + N_NODES;
}
__global__ void k_fill_csr(const int* __restrict__ row, const int* __restrict__ col) {
    int stride = gridDim.x * blockDim.x;
    for (int t = blockIdx.x * blockDim.x + threadIdx.x; t < E_EDGES + N_NODES; t += stride) {
        int v, srcv;
        if (t < E_EDGES) { v = col[t]; srcv = row[t]; }
        else             { v = t - E_EDGES; srcv = v; }
        int p = atomicAdd(&g_cursor[v], 1);
        g_csrsrc[p] = srcv;
    }
}

// ---------------- merged prep: fuse GEMM + transpose + bias + gstart ----------
// blocks [0,64): 32x32 fuse tiles (Wf = We@Wc0, stored fp16 [n][k])
// blocks [64,320): Wt16 transpose + bf + gstart by flat id
__global__ __launch_bounds__(256) void k_prep(const float* __restrict__ enc_W,
                                              const float* __restrict__ conv_W,
                                              const float* __restrict__ enc_b,
                                              const int* __restrict__ batch) {
    int tid = threadIdx.x;
    int b = blockIdx.x;
    if (b < 64) {
        __shared__ float sA[32][33], sB[32][33];
        int tx = tid & 31, ty = tid >> 5;            // 32 x 8
        int n0 = (b & 7) * 32, k0 = (b >> 3) * 32;
        float acc[4] = {0.f, 0.f, 0.f, 0.f};
        for (int j0 = 0; j0 < HID; j0 += 32) {
#pragma unroll
            for (int r = 0; r < 4; r++) {
                sA[ty + r * 8][tx] = enc_W[(k0 + ty + r * 8) * HID + j0 + tx];
                sB[ty + r * 8][tx] = conv_W[(j0 + ty + r * 8) * HID + n0 + tx];
            }
            __syncthreads();
#pragma unroll
            for (int j = 0; j < 32; j++) {
                float bb = sB[j][tx];
#pragma unroll
                for (int r = 0; r < 4; r++)
                    acc[r] += sA[ty + r * 8][j] * bb;
            }
            __syncthreads();
        }
#pragma unroll
        for (int r = 0; r < 4; r++)
            g_Wf16[(n0 + tx) * HID + k0 + ty + r * 8] = __float2half_rn(acc[r]);
    } else {
        int id = (b - 64) * 256 + tid;               // [0, 65536)
        {   // conv_W[1] transpose -> fp16 [N][K]
            int k = id >> 8, n = id & 255;
            g_Wt16[n * HID + k] = __float2half_rn(conv_W[HID * HID + id]);
        }
        if (id < HID) {      // bf[n] = sum_j enc_b[j] * conv_W0[j][n]
            float acc = 0.f;
            for (int j = 0; j < HID; j++)
                acc += enc_b[j] * conv_W[j * HID + id];
            g_bf[id] = acc;
        }
        if (id <= NGRAPH) {
            int lo = 0, hi = N_NODES;
            while (lo < hi) {
                int mid = (lo + hi) >> 1;
                if (batch[mid] < id) lo = mid + 1; else hi = mid;
            }
            g_gstart[id] = lo;
        }
    }
}

// ---------------- mma.sync GEMM: [M,256] @ [256,256], templated A dtype -------
// Output fp16: value = (acc [+ bias]) * dinv[row]   (pre-scaled for aggregation)
#define PWH 20
#define PWF 36
#define BTILE_B (128 * PWH * 4)                 // 10240
#define ATILE_H (128 * PWH * 4)                 // 10240
#define ATILE_F (128 * PWF * 4)                 // 18432
#define BUF_H (ATILE_H + BTILE_B)               // 20480
#define BUF_F (ATILE_F + BTILE_B)               // 28672
#define SMEM_H (2 * BUF_H)                      // 40960
#define SMEM_F (2 * BUF_F)                      // 57344

template <bool AFP32>
__global__ void __launch_bounds__(256, 2)
k_gemm(const void* __restrict__ Av, const __half* __restrict__ W,
       const float* __restrict__ bias, __half* __restrict__ C, int M) {
    extern __shared__ char smem[];
    uint32_t sb = smem_u32(smem);
    const int BUFB = AFP32 ? BUF_F : BUF_H;
    const int ATILE = AFP32 ? ATILE_F : ATILE_H;
    int tid = threadIdx.x;
    int lane = tid & 31, wid = tid >> 5;
    int warp_m = wid & 3, warp_n = wid >> 2;
    int g = lane >> 2, tig = lane & 3;
    int bm = blockIdx.x * 128;
    int bn = blockIdx.y * 128;

    float acc[2][8][4];
#pragma unroll
    for (int mt = 0; mt < 2; mt++)
#pragma unroll
        for (int nt = 0; nt < 8; nt++)
#pragma unroll
            for (int j = 0; j < 4; j++) acc[mt][nt][j] = 0.f;

    auto load_chunk = [&](int c, int buf) {
        int k0 = c * 32;
        uint32_t abase = sb + buf * BUFB;
        uint32_t bbase = abase + ATILE;
        if (AFP32) {
            const float* A = (const float*)Av;
#pragma unroll
            for (int i = 0; i < 4; i++) {
                int f = tid + i * 256;          // 0..1023
                int r = f >> 3, q = f & 7;
                int gr = bm + r;
                const float* src = A + (size_t)gr * HID + k0 + q * 4;
                uint32_t dst = abase + r * (PWF * 4) + q * 16;
                uint32_t sz = (gr < M) ? 16u : 0u;
                CP_ASYNC16(dst, src, sz);
            }
        } else {
            const __half* A = (const __half*)Av;
#pragma unroll
            for (int i = 0; i < 2; i++) {
                int f = tid + i * 256;          // 0..511
                int r = f >> 2, q = f & 3;
                int gr = bm + r;
                const __half* src = A + (size_t)gr * HID + k0 + q * 8;
                uint32_t dst = abase + r * (PWH * 4) + q * 16;
                uint32_t sz = (gr < M) ? 16u : 0u;
                CP_ASYNC16(dst, src, sz);
            }
        }
#pragma unroll
        for (int i = 0; i < 2; i++) {
            int f = tid + i * 256;
            int r = f >> 2, q = f & 3;          // n row 0..127
            const __half* src = W + (size_t)(bn + r) * HID + k0 + q * 8;
            uint32_t dst = bbase + r * (PWH * 4) + q * 16;
            CP_ASYNC16(dst, src, 16u);
        }
        CP_COMMIT();
    };

    load_chunk(0, 0);

    for (int c = 0; c < 8; c++) {
        int buf = c & 1;
        if (c < 7) {
            load_chunk(c + 1, buf ^ 1);
            CP_WAIT(1);
        } else {
            CP_WAIT(0);
        }
        __syncthreads();

        const char* base = smem + buf * BUFB;
        const uint32_t* Bs = (const uint32_t*)(base + ATILE);

#pragma unroll
        for (int ks = 0; ks < 2; ks++) {
            uint32_t afr[2][4];
            if (AFP32) {
                const float* Asf = (const float*)base;
                int ke = ks * 16 + 2 * tig;      // k element index
#pragma unroll
                for (int mt = 0; mt < 2; mt++) {
                    int m0 = warp_m * 32 + mt * 16;
                    float2 v0 = *(const float2*)&Asf[(m0 + g) * PWF + ke];
                    float2 v1 = *(const float2*)&Asf[(m0 + 8 + g) * PWF + ke];
                    float2 v2 = *(const float2*)&Asf[(m0 + g) * PWF + ke + 8];
                    float2 v3 = *(const float2*)&Asf[(m0 + 8 + g) * PWF + ke + 8];
                    afr[mt][0] = h2_bits(__floats2half2_rn(v0.x, v0.y));
                    afr[mt][1] = h2_bits(__floats2half2_rn(v1.x, v1.y));
                    afr[mt][2] = h2_bits(__floats2half2_rn(v2.x, v2.y));
                    afr[mt][3] = h2_bits(__floats2half2_rn(v3.x, v3.y));
                }
            } else {
                const uint32_t* As = (const uint32_t*)base;
                int kw = ks * 8;
#pragma unroll
                for (int mt = 0; mt < 2; mt++) {
                    int m0 = warp_m * 32 + mt * 16;
                    afr[mt][0] = As[(m0 + g) * PWH + kw + tig];
                    afr[mt][1] = As[(m0 + 8 + g) * PWH + kw + tig];
                    afr[mt][2] = As[(m0 + g) * PWH + kw + tig + 4];
                    afr[mt][3] = As[(m0 + 8 + g) * PWH + kw + tig + 4];
                }
            }
            int kw = ks * 8;
            uint32_t bfr[8][2];
#pragma unroll
            for (int nt = 0; nt < 8; nt++) {
                int n0 = warp_n * 64 + nt * 8;
                bfr[nt][0] = Bs[(n0 + g) * PWH + kw + tig];
                bfr[nt][1] = Bs[(n0 + g) * PWH + kw + tig + 4];
            }
#pragma unroll
            for (int mt = 0; mt < 2; mt++)
#pragma unroll
                for (int nt = 0; nt < 8; nt++)
                    mma_f16(acc[mt][nt], afr[mt], bfr[nt]);
        }
        __syncthreads();
    }

    // epilogue: (acc [+ bias]) * dinv[row] -> fp16
#pragma unroll
    for (int mt = 0; mt < 2; mt++) {
        int m_base = bm + warp_m * 32 + mt * 16;
        int row0 = m_base + g;
        int row1 = m_base + 8 + g;
        float s0 = (row0 < M) ? g_dinv[row0] : 0.f;
        float s1 = (row1 < M) ? g_dinv[row1] : 0.f;
#pragma unroll
        for (int nt = 0; nt < 8; nt++) {
            int n = bn + warp_n * 64 + nt * 8 + 2 * tig;
            float2 badd = make_float2(0.f, 0.f);
            if (bias) badd = *(const float2*)&bias[n];
            if (row0 < M)
                *(__half2*)&C[(size_t)row0 * HID + n] =
                    __floats2half2_rn((acc[mt][nt][0] + badd.x) * s0,
                                      (acc[mt][nt][1] + badd.y) * s0);
            if (row1 < M)
                *(__half2*)&C[(size_t)row1 * HID + n] =
                    __floats2half2_rn((acc[mt][nt][2] + badd.x) * s1,
                                      (acc[mt][nt][3] + badd.y) * s1);
        }
    }
}

// ---------------- pull-based aggregation (fp16 gather, fp32 accumulate) -------
// rows pre-scaled by dinv[src]; out = relu(dinv[v]*sum + b) in fp16.
// 64 threads/node, 4 nodes per 256-block, edge loop unrolled x2.
__global__ __launch_bounds__(256) void k_aggregate(const __half* __restrict__ h2,
                                                   const float* __restrict__ b,
                                                   __half* __restrict__ out) {
    int node = blockIdx.x * 4 + (threadIdx.x >> 6);
    int f4 = (threadIdx.x & 63) * 4;
    if (node >= N_NODES) return;

    int s = g_indptr[node];
    int e = g_indptr[node + 1];
    float dv = g_dinv[node];

    float4 acc = make_float4(0.f, 0.f, 0.f, 0.f);
    int i = s;
    for (; i + 1 < e; i += 2) {
        int s0 = g_csrsrc[i];
        int s1 = g_csrsrc[i + 1];
        uint2 p0 = *(const uint2*)&h2[(size_t)s0 * HID + f4];
        uint2 p1 = *(const uint2*)&h2[(size_t)s1 * HID + f4];
        float2 a0 = __half22float2(*(const __half2*)&p0.x);
        float2 c0 = __half22float2(*(const __half2*)&p0.y);
        float2 a1 = __half22float2(*(const __half2*)&p1.x);
        float2 c1 = __half22float2(*(const __half2*)&p1.y);
        acc.x += a0.x + a1.x;
        acc.y += a0.y + a1.y;
        acc.z += c0.x + c1.x;
        acc.w += c0.y + c1.y;
    }
    if (i < e) {
        int s0 = g_csrsrc[i];
        uint2 p0 = *(const uint2*)&h2[(size_t)s0 * HID + f4];
        float2 a0 = __half22float2(*(const __half2*)&p0.x);
        float2 c0 = __half22float2(*(const __half2*)&p0.y);
        acc.x += a0.x;
        acc.y += a0.y;
        acc.z += c0.x;
        acc.w += c0.y;
    }
    float4 bb = *(const float4*)&b[f4];
    uint2 o;
    *(__half2*)&o.x = __floats2half2_rn(fmaxf(acc.x * dv + bb.x, 0.f),
                                        fmaxf(acc.y * dv + bb.y, 0.f));
    *(__half2*)&o.y = __floats2half2_rn(fmaxf(acc.z * dv + bb.z, 0.f),
                                        fmaxf(acc.w * dv + bb.w, 0.f));
    *(uint2*)&out[(size_t)node * HID + f4] = o;
}

// ---------------- fused mean-pool + classifier --------------------------------
__global__ __launch_bounds__(256) void k_pool_cls(const __half* __restrict__ h,
                                                  const float* __restrict__ outW,
                                                  const float* __restrict__ outb,
                                                  float* __restrict__ out) {
    int g = blockIdx.x;
    int tid = threadIdx.x;
    __shared__ float sp[HID];

    int s = g_gstart[g];
    int e = g_gstart[g + 1];
    float acc = 0.f;
    for (int n = s; n < e; n++) acc += __half2float(h[(size_t)n * HID + tid]);
    float cnt = (float)(e - s);
    sp[tid] = acc / fmaxf(cnt, 1.0f);
    __syncthreads();

    if (tid < NCLASS) {
        float o = outb[tid];
#pragma unroll 8
        for (int f = 0; f < HID; f++) o += sp[f] * outW[f * NCLASS + tid];
        out[g * NCLASS + tid] = o;
    }
}

// ---------------- launch ------------------------------------------------------
extern "C" void kernel_launch(void* const* d_in, const int* in_sizes, int n_in,
                              void* d_out, int out_size) {
    const float* x      = (const float*)d_in[0];
    const int*   eidx   = (const int*)d_in[1];
    const int*   batch  = (const int*)d_in[2];
    const float* enc_W  = (const float*)d_in[3];
    const float* enc_b  = (const float*)d_in[4];
    const float* conv_W = (const float*)d_in[5];
    const float* conv_b = (const float*)d_in[6];
    const float* out_W  = (const float*)d_in[7];
    const float* out_b  = (const float*)d_in[8];
    float* out = (float*)d_out;

    const int* row = eidx;
    const int* col = eidx + E_EDGES;

    static cudaStream_t sB = nullptr;
    static cudaEvent_t evFork = nullptr, evDinv = nullptr, evCsr = nullptr;
    static bool init_done = false;
    if (!init_done) {
        cudaFuncSetAttribute(k_gemm<true>,  cudaFuncAttributeMaxDynamicSharedMemorySize, SMEM_F);
        cudaFuncSetAttribute(k_gemm<false>, cudaFuncAttributeMaxDynamicSharedMemorySize, SMEM_H);
        cudaStreamCreateWithFlags(&sB, cudaStreamNonBlocking);
        cudaEventCreateWithFlags(&evFork, cudaEventDisableTiming);
        cudaEventCreateWithFlags(&evDinv, cudaEventDisableTiming);
        cudaEventCreateWithFlags(&evCsr, cudaEventDisableTiming);
        init_done = true;
    }

    __half* g_hh_ptr;   cudaGetSymbolAddress((void**)&g_hh_ptr,   g_hh);
    __half* g_h2h_ptr;  cudaGetSymbolAddress((void**)&g_h2h_ptr,  g_h2h);
    __half* g_Wt16_ptr; cudaGetSymbolAddress((void**)&g_Wt16_ptr, g_Wt16);
    __half* g_Wf16_ptr; cudaGetSymbolAddress((void**)&g_Wf16_ptr, g_Wf16);
    float*  g_bf_ptr;   cudaGetSymbolAddress((void**)&g_bf_ptr,   g_bf);

    dim3 ggrid((N_NODES + 127) / 128, 2);

    // ---- fork: stream B builds degrees/CSR; stream 0 preps weights -----------
    cudaEventRecord(evFork, 0);
    cudaStreamWaitEvent(sB, evFork, 0);

    k_zero<<<(N_NODES + 255) / 256, 256, 0, sB>>>();
    k_count_deg<<<2048, 256, 0, sB>>>(col);
    k_scan<<<NB_SCAN, 1024, 0, sB>>>();       // produces g_dinv + indptr + cursor
    cudaEventRecord(evDinv, sB);
    k_fill_csr<<<2048, 256, 0, sB>>>(row, col);
    cudaEventRecord(evCsr, sB);

    // stream 0: merged weight prep; gemmF epilogue needs dinv
    k_prep<<<320, 256>>>(enc_W, conv_W, enc_b, batch);
    cudaStreamWaitEvent(0, evDinv, 0);
    k_gemm<true><<<ggrid, 256, SMEM_F>>>(x, g_Wf16_ptr, g_bf_ptr, g_h2h_ptr, N_NODES);

    // join: aggregation needs full CSR
    cudaStreamWaitEvent(0, evCsr, 0);

    k_aggregate<<<(N_NODES + 3) / 4, 256>>>(g_h2h_ptr, conv_b, g_hh_ptr);
    k_gemm<false><<<ggrid, 256, SMEM_H>>>(g_hh_ptr, g_Wt16_ptr, nullptr, g_h2h_ptr, N_NODES);
    k_aggregate<<<(N_NODES + 3) / 4, 256>>>(g_h2h_ptr, conv_b + HID, g_hh_ptr);
    k_pool_cls<<<NGRAPH, 256>>>(g_hh_ptr, out_W, out_b, out);
}

// round 17
// speedup vs baseline: 1.0051x; 1.0051x over previous
#include <cuda_runtime.h>
#include <cuda_fp16.h>
#include <math.h>
#include <stdint.h>

#define N_NODES 50000
#define E_EDGES 800000
#define HID 256
#define NCLASS 10
#define NGRAPH 512
#define NB_SCAN ((N_NODES + 1023) / 1024)   // 49

// ---------------- device scratch (static; no cudaMalloc allowed) --------------
__device__ __half  g_hh[(size_t)N_NODES * HID];     // fp16 activations (agg out)
__device__ __half  g_h2h[(size_t)N_NODES * HID];    // fp16 pre-agg (dinv-scaled)
__device__ __half  g_Wt16[HID * HID];               // conv_W[1] fp16, [N][K]
__device__ __half  g_Wf16[HID * HID];               // fused We@Wc0 fp16, [N][K]
__device__ float   g_bf[HID];                       // fused bias be@Wc0
__device__ float   g_dinv[N_NODES];
__device__ int     g_deg[N_NODES];
__device__ int     g_indptr[N_NODES + 1];
__device__ int     g_cursor[N_NODES];
__device__ int     g_csrsrc[E_EDGES + N_NODES];
__device__ int     g_gstart[NGRAPH + 1];
__device__ int     g_part[64];

// ---------------- helpers -----------------------------------------------------
__device__ __forceinline__ uint32_t smem_u32(const void* p) {
    uint32_t a;
    asm("{ .reg .u64 t; cvta.to.shared.u64 t, %1; cvt.u32.u64 %0, t; }" : "=r"(a) : "l"(p));
    return a;
}
__device__ __forceinline__ uint32_t h2_bits(__half2 h) {
    return *(uint32_t*)&h;
}
__device__ __forceinline__ void mma_f16(float* d, const uint32_t* a, const uint32_t* b) {
    asm volatile(
        "mma.sync.aligned.m16n8k16.row.col.f32.f16.f16.f32 "
        "{%0,%1,%2,%3}, {%4,%5,%6,%7}, {%8,%9}, {%0,%1,%2,%3};"
        : "+f"(d[0]), "+f"(d[1]), "+f"(d[2]), "+f"(d[3])
        : "r"(a[0]), "r"(a[1]), "r"(a[2]), "r"(a[3]), "r"(b[0]), "r"(b[1]));
}
#define CP_ASYNC16(dst, src, sz) \
    asm volatile("cp.async.cg.shared.global [%0], [%1], 16, %2;" :: "r"(dst), "l"(src), "r"(sz))
#define CP_COMMIT()   asm volatile("cp.async.commit_group;" ::: "memory")
#define CP_WAIT(n)    asm volatile("cp.async.wait_group %0;" :: "n"(n) : "memory")

// ---------------- CSR pipeline (stream B) -------------------------------------
__global__ void k_zero() {
    int i = blockIdx.x * blockDim.x + threadIdx.x;
    if (i < N_NODES) g_deg[i] = 0;
    if (i < 64) g_part[i] = 0;
}
// vectorized: int2 per thread (E_EDGES = 800000 is even)
__global__ void k_count_deg(const int* __restrict__ col) {
    int stride = gridDim.x * blockDim.x;
    for (int e = blockIdx.x * blockDim.x + threadIdx.x; e < E_EDGES / 2; e += stride) {
        int2 c = ((const int2*)col)[e];
        atomicAdd(&g_deg[c.x], 1);
        atomicAdd(&g_deg[c.y], 1);
    }
}
// single-pass multi-block scan: local smem scan + published totals + spin.
// 49 blocks of 1024 all resident (148 SMs) -> no deadlock.
__global__ void k_scan() {
    __shared__ int s[1024];
    __shared__ int ssum;
    int tid = threadIdx.x;
    int bid = blockIdx.x;
    int i = bid * 1024 + tid;
    int v = 0;
    if (i < N_NODES) {
        int d = g_deg[i] + 1;
        v = d;
        g_dinv[i] = rsqrtf((float)d);
    }
    s[tid] = v;
    __syncthreads();
    for (int off = 1; off < 1024; off <<= 1) {
        int t = (tid >= off) ? s[tid - off] : 0;
        __syncthreads();
        s[tid] += t;
        __syncthreads();
    }
    if (tid == 0) {
        ssum = 0;
        __threadfence();
        g_part[bid] = s[1023];   // totals always >= 1: nonzero doubles as ready flag
    }
    __syncthreads();
    int off = 0;
    if (tid < bid) {             // bid <= 48 < 1024
        int pv;
        do { pv = ((volatile int*)g_part)[tid]; } while (pv == 0);
        off = pv;
    }
    if (off) atomicAdd(&ssum, off);
    __syncthreads();
    int base = ssum;
    if (i < N_NODES) {
        int val = base + s[tid] - v;
        g_indptr[i] = val;
        g_cursor[i] = val;
    }
    if (i == 0) g_indptr[N_NODES] = E_EDGES + N_NODES;
}
// vectorized: int2 loads of row/col; self-loops handled in tail range
__global__ void k_fill_csr(const int* __restrict__ row, const int* __restrict__ col) {
    int stride = gridDim.x * blockDim.x;
    int tid0 = blockIdx.x * blockDim.x + threadIdx.x;
    for (int t = tid0; t < E_EDGES / 2; t += stride) {
        int2 c = ((const int2*)col)[t];
        int2 r = ((const int2*)row)[t];
        int p0 = atomicAdd(&g_cursor[c.x], 1);
        g_csrsrc[p0] = r.x;
        int p1 = atomicAdd(&g_cursor[c.y], 1);
        g_csrsrc[p1] = r.y;
    }
    for (int t = tid0; t < N_NODES; t += stride) {   // self loops
        int p = atomicAdd(&g_cursor[t], 1);
        g_csrsrc[p] = t;
    }
}

// ---------------- merged prep: fuse GEMM + transpose + bias + gstart ----------
__global__ __launch_bounds__(256) void k_prep(const float* __restrict__ enc_W,
                                              const float* __restrict__ conv_W,
                                              const float* __restrict__ enc_b,
                                              const int* __restrict__ batch) {
    int tid = threadIdx.x;
    int b = blockIdx.x;
    if (b < 64) {
        __shared__ float sA[32][33], sB[32][33];
        int tx = tid & 31, ty = tid >> 5;            // 32 x 8
        int n0 = (b & 7) * 32, k0 = (b >> 3) * 32;
        float acc[4] = {0.f, 0.f, 0.f, 0.f};
        for (int j0 = 0; j0 < HID; j0 += 32) {
#pragma unroll
            for (int r = 0; r < 4; r++) {
                sA[ty + r * 8][tx] = enc_W[(k0 + ty + r * 8) * HID + j0 + tx];
                sB[ty + r * 8][tx] = conv_W[(j0 + ty + r * 8) * HID + n0 + tx];
            }
            __syncthreads();
#pragma unroll
            for (int j = 0; j < 32; j++) {
                float bb = sB[j][tx];
#pragma unroll
                for (int r = 0; r < 4; r++)
                    acc[r] += sA[ty + r * 8][j] * bb;
            }
            __syncthreads();
        }
#pragma unroll
        for (int r = 0; r < 4; r++)
            g_Wf16[(n0 + tx) * HID + k0 + ty + r * 8] = __float2half_rn(acc[r]);
    } else {
        int id = (b - 64) * 256 + tid;               // [0, 65536)
        {   // conv_W[1] transpose -> fp16 [N][K]
            int k = id >> 8, n = id & 255;
            g_Wt16[n * HID + k] = __float2half_rn(conv_W[HID * HID + id]);
        }
        if (id < HID) {      // bf[n] = sum_j enc_b[j] * conv_W0[j][n]
            float acc = 0.f;
            for (int j = 0; j < HID; j++)
                acc += enc_b[j] * conv_W[j * HID + id];
            g_bf[id] = acc;
        }
        if (id <= NGRAPH) {
            int lo = 0, hi = N_NODES;
            while (lo < hi) {
                int mid = (lo + hi) >> 1;
                if (batch[mid] < id) lo = mid + 1; else hi = mid;
            }
            g_gstart[id] = lo;
        }
    }
}

// ---------------- mma.sync GEMM: [M,256] @ [256,256], templated A dtype -------
// Output fp16: value = (acc [+ bias]) * dinv[row]   (pre-scaled for aggregation)
#define PWH 20
#define PWF 36
#define BTILE_B (128 * PWH * 4)                 // 10240
#define ATILE_H (128 * PWH * 4)                 // 10240
#define ATILE_F (128 * PWF * 4)                 // 18432
#define BUF_H (ATILE_H + BTILE_B)               // 20480
#define BUF_F (ATILE_F + BTILE_B)               // 28672
#define SMEM_H (2 * BUF_H)                      // 40960
#define SMEM_F (2 * BUF_F)                      // 57344

template <bool AFP32>
__global__ void __launch_bounds__(256, 2)
k_gemm(const void* __restrict__ Av, const __half* __restrict__ W,
       const float* __restrict__ bias, __half* __restrict__ C, int M) {
    extern __shared__ char smem[];
    uint32_t sb = smem_u32(smem);
    const int BUFB = AFP32 ? BUF_F : BUF_H;
    const int ATILE = AFP32 ? ATILE_F : ATILE_H;
    int tid = threadIdx.x;
    int lane = tid & 31, wid = tid >> 5;
    int warp_m = wid & 3, warp_n = wid >> 2;
    int g = lane >> 2, tig = lane & 3;
    int bm = blockIdx.x * 128;
    int bn = blockIdx.y * 128;

    float acc[2][8][4];
#pragma unroll
    for (int mt = 0; mt < 2; mt++)
#pragma unroll
        for (int nt = 0; nt < 8; nt++)
#pragma unroll
            for (int j = 0; j < 4; j++) acc[mt][nt][j] = 0.f;

    auto load_chunk = [&](int c, int buf) {
        int k0 = c * 32;
        uint32_t abase = sb + buf * BUFB;
        uint32_t bbase = abase + ATILE;
        if (AFP32) {
            const float* A = (const float*)Av;
#pragma unroll
            for (int i = 0; i < 4; i++) {
                int f = tid + i * 256;          // 0..1023
                int r = f >> 3, q = f & 7;
                int gr = bm + r;
                const float* src = A + (size_t)gr * HID + k0 + q * 4;
                uint32_t dst = abase + r * (PWF * 4) + q * 16;
                uint32_t sz = (gr < M) ? 16u : 0u;
                CP_ASYNC16(dst, src, sz);
            }
        } else {
            const __half* A = (const __half*)Av;
#pragma unroll
            for (int i = 0; i < 2; i++) {
                int f = tid + i * 256;          // 0..511
                int r = f >> 2, q = f & 3;
                int gr = bm + r;
                const __half* src = A + (size_t)gr * HID + k0 + q * 8;
                uint32_t dst = abase + r * (PWH * 4) + q * 16;
                uint32_t sz = (gr < M) ? 16u : 0u;
                CP_ASYNC16(dst, src, sz);
            }
        }
#pragma unroll
        for (int i = 0; i < 2; i++) {
            int f = tid + i * 256;
            int r = f >> 2, q = f & 3;          // n row 0..127
            const __half* src = W + (size_t)(bn + r) * HID + k0 + q * 8;
            uint32_t dst = bbase + r * (PWH * 4) + q * 16;
            CP_ASYNC16(dst, src, 16u);
        }
        CP_COMMIT();
    };

    load_chunk(0, 0);

    for (int c = 0; c < 8; c++) {
        int buf = c & 1;
        if (c < 7) {
            load_chunk(c + 1, buf ^ 1);
            CP_WAIT(1);
        } else {
            CP_WAIT(0);
        }
        __syncthreads();

        const char* base = smem + buf * BUFB;
        const uint32_t* Bs = (const uint32_t*)(base + ATILE);

#pragma unroll
        for (int ks = 0; ks < 2; ks++) {
            uint32_t afr[2][4];
            if (AFP32) {
                const float* Asf = (const float*)base;
                int ke = ks * 16 + 2 * tig;      // k element index
#pragma unroll
                for (int mt = 0; mt < 2; mt++) {
                    int m0 = warp_m * 32 + mt * 16;
                    float2 v0 = *(const float2*)&Asf[(m0 + g) * PWF + ke];
                    float2 v1 = *(const float2*)&Asf[(m0 + 8 + g) * PWF + ke];
                    float2 v2 = *(const float2*)&Asf[(m0 + g) * PWF + ke + 8];
                    float2 v3 = *(const float2*)&Asf[(m0 + 8 + g) * PWF + ke + 8];
                    afr[mt][0] = h2_bits(__floats2half2_rn(v0.x, v0.y));
                    afr[mt][1] = h2_bits(__floats2half2_rn(v1.x, v1.y));
                    afr[mt][2] = h2_bits(__floats2half2_rn(v2.x, v2.y));
                    afr[mt][3] = h2_bits(__floats2half2_rn(v3.x, v3.y));
                }
            } else {
                const uint32_t* As = (const uint32_t*)base;
                int kw = ks * 8;
#pragma unroll
                for (int mt = 0; mt < 2; mt++) {
                    int m0 = warp_m * 32 + mt * 16;
                    afr[mt][0] = As[(m0 + g) * PWH + kw + tig];
                    afr[mt][1] = As[(m0 + 8 + g) * PWH + kw + tig];
                    afr[mt][2] = As[(m0 + g) * PWH + kw + tig + 4];
                    afr[mt][3] = As[(m0 + 8 + g) * PWH + kw + tig + 4];
                }
            }
            int kw = ks * 8;
            uint32_t bfr[8][2];
#pragma unroll
            for (int nt = 0; nt < 8; nt++) {
                int n0 = warp_n * 64 + nt * 8;
                bfr[nt][0] = Bs[(n0 + g) * PWH + kw + tig];
                bfr[nt][1] = Bs[(n0 + g) * PWH + kw + tig + 4];
            }
#pragma unroll
            for (int mt = 0; mt < 2; mt++)
#pragma unroll
                for (int nt = 0; nt < 8; nt++)
                    mma_f16(acc[mt][nt], afr[mt], bfr[nt]);
        }
        __syncthreads();
    }

    // epilogue: (acc [+ bias]) * dinv[row] -> fp16
#pragma unroll
    for (int mt = 0; mt < 2; mt++) {
        int m_base = bm + warp_m * 32 + mt * 16;
        int row0 = m_base + g;
        int row1 = m_base + 8 + g;
        float s0 = (row0 < M) ? g_dinv[row0] : 0.f;
        float s1 = (row1 < M) ? g_dinv[row1] : 0.f;
#pragma unroll
        for (int nt = 0; nt < 8; nt++) {
            int n = bn + warp_n * 64 + nt * 8 + 2 * tig;
            float2 badd = make_float2(0.f, 0.f);
            if (bias) badd = *(const float2*)&bias[n];
            if (row0 < M)
                *(__half2*)&C[(size_t)row0 * HID + n] =
                    __floats2half2_rn((acc[mt][nt][0] + badd.x) * s0,
                                      (acc[mt][nt][1] + badd.y) * s0);
            if (row1 < M)
                *(__half2*)&C[(size_t)row1 * HID + n] =
                    __floats2half2_rn((acc[mt][nt][2] + badd.x) * s1,
                                      (acc[mt][nt][3] + badd.y) * s1);
        }
    }
}

// ---------------- pull-based aggregation (fp16 gather, fp32 accumulate) -------
// rows pre-scaled by dinv[src]; out = relu(dinv[v]*sum + b) in fp16.
// 64 threads/node, 4 nodes per 256-block, edge loop unrolled x4 for MLP.
__global__ __launch_bounds__(256) void k_aggregate(const __half* __restrict__ h2,
                                                   const float* __restrict__ b,
                                                   __half* __restrict__ out) {
    int node = blockIdx.x * 4 + (threadIdx.x >> 6);
    int f4 = (threadIdx.x & 63) * 4;
    if (node >= N_NODES) return;

    int s = g_indptr[node];
    int e = g_indptr[node + 1];
    float dv = g_dinv[node];

    float4 acc = make_float4(0.f, 0.f, 0.f, 0.f);
    int i = s;
    for (; i + 3 < e; i += 4) {
        int s0 = g_csrsrc[i];
        int s1 = g_csrsrc[i + 1];
        int s2 = g_csrsrc[i + 2];
        int s3 = g_csrsrc[i + 3];
        uint2 p0 = *(const uint2*)&h2[(size_t)s0 * HID + f4];
        uint2 p1 = *(const uint2*)&h2[(size_t)s1 * HID + f4];
        uint2 p2 = *(const uint2*)&h2[(size_t)s2 * HID + f4];
        uint2 p3 = *(const uint2*)&h2[(size_t)s3 * HID + f4];
        float2 a0 = __half22float2(*(const __half2*)&p0.x);
        float2 c0 = __half22float2(*(const __half2*)&p0.y);
        float2 a1 = __half22float2(*(const __half2*)&p1.x);
        float2 c1 = __half22float2(*(const __half2*)&p1.y);
        float2 a2 = __half22float2(*(const __half2*)&p2.x);
        float2 c2 = __half22float2(*(const __half2*)&p2.y);
        float2 a3 = __half22float2(*(const __half2*)&p3.x);
        float2 c3 = __half22float2(*(const __half2*)&p3.y);
        acc.x += (a0.x + a1.x) + (a2.x + a3.x);
        acc.y += (a0.y + a1.y) + (a2.y + a3.y);
        acc.z += (c0.x + c1.x) + (c2.x + c3.x);
        acc.w += (c0.y + c1.y) + (c2.y + c3.y);
    }
    for (; i < e; i++) {
        int s0 = g_csrsrc[i];
        uint2 p0 = *(const uint2*)&h2[(size_t)s0 * HID + f4];
        float2 a0 = __half22float2(*(const __half2*)&p0.x);
        float2 c0 = __half22float2(*(const __half2*)&p0.y);
        acc.x += a0.x;
        acc.y += a0.y;
        acc.z += c0.x;
        acc.w += c0.y;
    }
    float4 bb = *(const float4*)&b[f4];
    uint2 o;
    *(__half2*)&o.x = __floats2half2_rn(fmaxf(acc.x * dv + bb.x, 0.f),
                                        fmaxf(acc.y * dv + bb.y, 0.f));
    *(__half2*)&o.y = __floats2half2_rn(fmaxf(acc.z * dv + bb.z, 0.f),
                                        fmaxf(acc.w * dv + bb.w, 0.f));
    *(uint2*)&out[(size_t)node * HID + f4] = o;
}

// ---------------- fused mean-pool + classifier --------------------------------
__global__ __launch_bounds__(256) void k_pool_cls(const __half* __restrict__ h,
                                                  const float* __restrict__ outW,
                                                  const float* __restrict__ outb,
                                                  float* __restrict__ out) {
    int g = blockIdx.x;
    int tid = threadIdx.x;
    __shared__ float sp[HID];

    int s = g_gstart[g];
    int e = g_gstart[g + 1];
    float acc = 0.f;
    for (int n = s; n < e; n++) acc += __half2float(h[(size_t)n * HID + tid]);
    float cnt = (float)(e - s);
    sp[tid] = acc / fmaxf(cnt, 1.0f);
    __syncthreads();

    if (tid < NCLASS) {
        float o = outb[tid];
#pragma unroll 8
        for (int f = 0; f < HID; f++) o += sp[f] * outW[f * NCLASS + tid];
        out[g * NCLASS + tid] = o;
    }
}

// ---------------- launch ------------------------------------------------------
extern "C" void kernel_launch(void* const* d_in, const int* in_sizes, int n_in,
                              void* d_out, int out_size) {
    const float* x      = (const float*)d_in[0];
    const int*   eidx   = (const int*)d_in[1];
    const int*   batch  = (const int*)d_in[2];
    const float* enc_W  = (const float*)d_in[3];
    const float* enc_b  = (const float*)d_in[4];
    const float* conv_W = (const float*)d_in[5];
    const float* conv_b = (const float*)d_in[6];
    const float* out_W  = (const float*)d_in[7];
    const float* out_b  = (const float*)d_in[8];
    float* out = (float*)d_out;

    const int* row = eidx;
    const int* col = eidx + E_EDGES;

    static cudaStream_t sB = nullptr;
    static cudaEvent_t evFork = nullptr, evDinv = nullptr, evCsr = nullptr;
    static bool init_done = false;
    if (!init_done) {
        cudaFuncSetAttribute(k_gemm<true>,  cudaFuncAttributeMaxDynamicSharedMemorySize, SMEM_F);
        cudaFuncSetAttribute(k_gemm<false>, cudaFuncAttributeMaxDynamicSharedMemorySize, SMEM_H);
        cudaStreamCreateWithFlags(&sB, cudaStreamNonBlocking);
        cudaEventCreateWithFlags(&evFork, cudaEventDisableTiming);
        cudaEventCreateWithFlags(&evDinv, cudaEventDisableTiming);
        cudaEventCreateWithFlags(&evCsr, cudaEventDisableTiming);
        init_done = true;
    }

    __half* g_hh_ptr;   cudaGetSymbolAddress((void**)&g_hh_ptr,   g_hh);
    __half* g_h2h_ptr;  cudaGetSymbolAddress((void**)&g_h2h_ptr,  g_h2h);
    __half* g_Wt16_ptr; cudaGetSymbolAddress((void**)&g_Wt16_ptr, g_Wt16);
    __half* g_Wf16_ptr; cudaGetSymbolAddress((void**)&g_Wf16_ptr, g_Wf16);
    float*  g_bf_ptr;   cudaGetSymbolAddress((void**)&g_bf_ptr,   g_bf);

    dim3 ggrid((N_NODES + 127) / 128, 2);

    // ---- fork: stream B builds degrees/CSR; stream 0 preps weights -----------
    cudaEventRecord(evFork, 0);
    cudaStreamWaitEvent(sB, evFork, 0);

    k_zero<<<(N_NODES + 255) / 256, 256, 0, sB>>>();
    k_count_deg<<<1024, 256, 0, sB>>>(col);
    k_scan<<<NB_SCAN, 1024, 0, sB>>>();       // produces g_dinv + indptr + cursor
    cudaEventRecord(evDinv, sB);
    k_fill_csr<<<1024, 256, 0, sB>>>(row, col);
    cudaEventRecord(evCsr, sB);

    // stream 0: merged weight prep; gemmF epilogue needs dinv
    k_prep<<<320, 256>>>(enc_W, conv_W, enc_b, batch);
    cudaStreamWaitEvent(0, evDinv, 0);
    k_gemm<true><<<ggrid, 256, SMEM_F>>>(x, g_Wf16_ptr, g_bf_ptr, g_h2h_ptr, N_NODES);

    // join: aggregation needs full CSR
    cudaStreamWaitEvent(0, evCsr, 0);

    k_aggregate<<<(N_NODES + 3) / 4, 256>>>(g_h2h_ptr, conv_b, g_hh_ptr);
    k_gemm<false><<<ggrid, 256, SMEM_H>>>(g_hh_ptr, g_Wt16_ptr, nullptr, g_h2h_ptr, N_NODES);
    k_aggregate<<<(N_NODES + 3) / 4, 256>>>(g_h2h_ptr, conv_b + HID, g_hh_ptr);
    k_pool_cls<<<NGRAPH, 256>>>(g_hh_ptr, out_W, out_b, out);
}